// round 10
// baseline (speedup 1.0000x reference)
#include <cuda_runtime.h>
#include <cuda_bf16.h>
#include <cstdint>

// DotProductAttention B=8,H=8,N=2048,D=64 fp32 — R7.
// = R5 hot loop (x2 ldmatrix, benched 293.6us) + Pade softmax (1 ex2 + 1 rcp)
//   + convert_kv early-exit + exact pad-bias correction.
// (R6's ldsm.x4 restructure reverted: register-pressure regression under the
//  128-reg cap of __launch_bounds__(256,2).)

#define SM_QHI 0
#define SM_QLO 16384
#define SM_KV  32768            // 2 stages x 32KB: [KHI|KLO|VHI|VLO] 8KB each
#define STAGE  32768
#define SM_TOTAL (SM_KV + 2 * STAGE)   // 96KB

#define EXP_M10 4.5399929762e-05f      // e^-10 (pad-slot p value)

__device__ int g_cnt[8];
__device__ int g_idx[8][2048];
__device__ unsigned char KCH[1 << 24];   // 16MB each: [bh][slot][64 bf16]
__device__ unsigned char KCL[1 << 24];
__device__ unsigned char VCH[1 << 24];
__device__ unsigned char VCL[1 << 24];

// ---- pass 1: deterministic per-batch compaction of unmasked keys ----
__global__ void build_idx(const unsigned char* __restrict__ mraw)
{
    const int b = blockIdx.x;
    const int t = threadIdx.x;                 // 1024 threads
    __shared__ int wsum[32];

    int mynz = 0;
#pragma unroll
    for (int k = 0; k < 4; k++) {
        int i = t * 4 + k;
        if ((i & 3) && mraw[i]) mynz = 1;
    }
    const int is_u8 = __syncthreads_or(mynz);  // bool-as-u8 vs bool-as-i32

    int m0, m1;
    if (is_u8) {
        m0 = mraw[b * 2048 + 2 * t];
        m1 = mraw[b * 2048 + 2 * t + 1];
    } else {
        const int* mi = (const int*)mraw;
        m0 = mi[b * 2048 + 2 * t];
        m1 = mi[b * 2048 + 2 * t + 1];
    }
    const int f0 = (m0 == 0), f1 = (m1 == 0);
    const int pair = f0 + f1;
    const int lane = t & 31, w = t >> 5;

    int sc = pair;
#pragma unroll
    for (int d = 1; d < 32; d <<= 1) {
        int v = __shfl_up_sync(0xffffffffu, sc, d);
        if (lane >= d) sc += v;
    }
    if (lane == 31) wsum[w] = sc;
    __syncthreads();
    if (w == 0) {
        int s2 = wsum[lane];
#pragma unroll
        for (int d = 1; d < 32; d <<= 1) {
            int u = __shfl_up_sync(0xffffffffu, s2, d);
            if (lane >= d) s2 += u;
        }
        wsum[lane] = s2;
    }
    __syncthreads();
    int base = (w ? wsum[w - 1] : 0) + sc - pair;
    if (f0) g_idx[b][base++] = 2 * t;
    if (f1) g_idx[b][base] = 2 * t + 1;
    if (t == 0) g_cnt[b] = wsum[31];
}

// ---- helpers ----
__device__ __forceinline__ uint32_t smem_u32(const void* p) {
    uint32_t a;
    asm("{ .reg .u64 t; cvta.to.shared.u64 t, %1; cvt.u32.u64 %0, t; }" : "=r"(a) : "l"(p));
    return a;
}
__device__ __forceinline__ void split2(float a, float b, uint32_t& hi, uint32_t& lo) {
    uint32_t h;
    asm("cvt.rn.bf16x2.f32 %0, %1, %2;" : "=r"(h) : "f"(b), "f"(a));
    float ah = __uint_as_float(h << 16);
    float bh = __uint_as_float(h & 0xffff0000u);
    asm("cvt.rn.bf16x2.f32 %0, %1, %2;" : "=r"(lo) : "f"(b - bh), "f"(a - ah));
    hi = h;
}
__device__ __forceinline__ void mma_bf16(float* d, const uint32_t* a, const uint32_t* b) {
    asm volatile("mma.sync.aligned.m16n8k16.row.col.f32.bf16.bf16.f32 "
                 "{%0,%1,%2,%3}, {%4,%5,%6,%7}, {%8,%9}, {%0,%1,%2,%3};"
                 : "+f"(d[0]), "+f"(d[1]), "+f"(d[2]), "+f"(d[3])
                 : "r"(a[0]), "r"(a[1]), "r"(a[2]), "r"(a[3]), "r"(b[0]), "r"(b[1]));
}
__device__ __forceinline__ void ldsm2(uint32_t& r0, uint32_t& r1, uint32_t addr) {
    asm volatile("ldmatrix.sync.aligned.m8n8.x2.shared.b16 {%0,%1}, [%2];"
                 : "=r"(r0), "=r"(r1) : "r"(addr));
}
__device__ __forceinline__ void ldsm2t(uint32_t& r0, uint32_t& r1, uint32_t addr) {
    asm volatile("ldmatrix.sync.aligned.m8n8.x2.trans.shared.b16 {%0,%1}, [%2];"
                 : "=r"(r0), "=r"(r1) : "r"(addr));
}
__device__ __forceinline__ void ldsm4(uint32_t* r, uint32_t addr) {
    asm volatile("ldmatrix.sync.aligned.m8n8.x4.shared.b16 {%0,%1,%2,%3}, [%4];"
                 : "=r"(r[0]), "=r"(r[1]), "=r"(r[2]), "=r"(r[3]) : "r"(addr));
}
__device__ __forceinline__ float ex2f(float x) {
    float r;
    asm("ex2.approx.f32 %0, %1;" : "=f"(r) : "f"(x));
    return r;
}
__device__ __forceinline__ float rcpf(float x) {
    float r;
    asm("rcp.approx.f32 %0, %1;" : "=f"(r) : "f"(x));
    return r;
}
// p = exp(10*tanh(s/8) - 10) via Pade[7/6] tanh (coeffs pre-scaled for u = s)
__device__ __forceinline__ float softmax_p(float s) {
    float u = fminf(fmaxf(s, -39.2f), 39.2f);
    float y = u * u;
    float pn = fmaf(fmaf(fmaf(3.8146973e-6f, y, 0.092285156f), y, 270.703125f), y, 135135.0f);
    float qd = fmaf(fmaf(fmaf(1.0681152e-4f, y, 0.769042969f), y, 974.53125f), y, 135135.0f);
    float r  = pn * rcpf(qd);
    // 10/8*log2(e) = 1.8033688 ;  10*log2(e) = 14.4269504
    return ex2f(fmaf(1.8033688f * u, r, -14.4269504f));
}

// ---- pass 2: gather + convert K/V to bf16 hi/lo in compacted order ----
__global__ void __launch_bounds__(256)
convert_kv(const float* __restrict__ K, const float* __restrict__ V)
{
    const int bh = blockIdx.y, b = bh >> 3;
    const int cnt = g_cnt[b];
    const int padded = (cnt + 63) & ~63;
    const int slot = blockIdx.x * 16 + (threadIdx.x >> 4);
    if (slot >= padded) return;                // beyond padded region: never read
    const int c4 = (threadIdx.x & 15) << 2;
    const size_t doff = ((((size_t)bh << 11) + slot) << 7) + c4 * 2;  // byte offset
    uint32_t kh0 = 0, kl0 = 0, kh1 = 0, kl1 = 0;
    uint32_t vh0 = 0, vl0 = 0, vh1 = 0, vl1 = 0;
    if (slot < cnt) {
        const int row = g_idx[b][slot];
        const float4 kk = *(const float4*)(K + ((((size_t)bh << 11) + row) << 6) + c4);
        const float4 vv = *(const float4*)(V + ((((size_t)bh << 11) + row) << 6) + c4);
        split2(kk.x, kk.y, kh0, kl0); split2(kk.z, kk.w, kh1, kl1);
        split2(vv.x, vv.y, vh0, vl0); split2(vv.z, vv.w, vh1, vl1);
    }
    *(uint2*)(KCH + doff) = make_uint2(kh0, kh1);
    *(uint2*)(KCL + doff) = make_uint2(kl0, kl1);
    *(uint2*)(VCH + doff) = make_uint2(vh0, vh1);
    *(uint2*)(VCL + doff) = make_uint2(vl0, vl1);
}

// ---- cp.async staging of one 64-key tile (K/V hi/lo) into a smem stage ----
__device__ __forceinline__ void stage_tile(uint32_t sdst, int bh, int kv0, int tid)
{
#pragma unroll
    for (int it = 0; it < 8; it++) {
        const int tensor = it >> 1;
        const int cc = ((it & 1) << 8) + tid;            // 0..511
        const int r = cc >> 3, ch = cc & 7;
        const unsigned char* g = (tensor == 0) ? KCH : (tensor == 1) ? KCL
                               : (tensor == 2) ? VCH : VCL;
        const unsigned char* src = g + ((((size_t)bh << 11) + kv0 + r) << 7) + (ch << 4);
        uint32_t dst = sdst + tensor * 8192 + r * 128 + ((ch ^ (r & 7)) << 4);
        asm volatile("cp.async.cg.shared.global [%0], [%1], 16;"
                     :: "r"(dst), "l"(src) : "memory");
    }
}
#define CP_COMMIT() asm volatile("cp.async.commit_group;" ::: "memory")
#define CP_WAIT0()  asm volatile("cp.async.wait_group 0;" ::: "memory")

// ---- main kernel: 256 threads, 8 warps, 128 q-rows per CTA ----
__global__ void __launch_bounds__(256, 2)
attn_mma(const float* __restrict__ Q, float* __restrict__ out)
{
    extern __shared__ char smem[];
    const uint32_t sb = smem_u32(smem);

    const int tid  = threadIdx.x;
    const int warp = tid >> 5;
    const int lane = tid & 31;
    const int gid  = lane >> 2;
    const int tig  = lane & 3;
    const int R0   = warp << 4;

    const int bh = blockIdx.y;
    const int b  = bh >> 3;
    const int q0 = blockIdx.x << 7;      // 128-row q tile

    const int cnt    = g_cnt[b];
    const int ntiles = (cnt + 63) >> 6;

    const float* Qg = Q + ((((size_t)bh << 11) + q0) << 6);

    // stage tile 0 first (overlaps with Q conversion below)
    stage_tile(sb + SM_KV, bh, 0, tid);
    CP_COMMIT();

    // ---- Q -> smem (hi/lo bf16, XOR swizzle) ----
#pragma unroll
    for (int it = 0; it < 8; it++) {
        int idx = it * 256 + tid;        // 2048 float4 slots: 128 rows x 16
        int r   = idx >> 4;
        int c4  = (idx & 15) << 2;
        float4 v = *(const float4*)(Qg + (r << 6) + c4);
        uint32_t h0, l0, h1, l1;
        split2(v.x, v.y, h0, l0);
        split2(v.z, v.w, h1, l1);
        uint32_t off = r * 128 + ((c4 * 2) ^ ((r & 7) << 4));
        *(uint2*)(smem + SM_QHI + off) = make_uint2(h0, h1);
        *(uint2*)(smem + SM_QLO + off) = make_uint2(l0, l1);
    }
    __syncthreads();

    // ---- Q A-fragments in registers for the whole kernel ----
    uint32_t qh[4][4], ql[4][4];
    {
        const int arow = R0 + (lane & 7) + ((lane >> 3) & 1) * 8;
        const int asw  = lane & 7;
#pragma unroll
        for (int kk = 0; kk < 4; kk++) {
            uint32_t off = arow * 128 + ((((2 * kk + (lane >> 4)) ^ asw)) << 4);
            ldsm4(qh[kk], sb + SM_QHI + off);
            ldsm4(ql[kk], sb + SM_QLO + off);
        }
    }

    float o[8][4];
#pragma unroll
    for (int j = 0; j < 8; j++)
#pragma unroll
        for (int e = 0; e < 4; e++) o[j][e] = 0.0f;
    float lsum_lo = 0.0f, lsum_hi = 0.0f;

    const int krow = lane & 7;
    const int ksel = (lane >> 3) & 1;
    const int vrow = (lane & 7) + ((lane >> 3) & 1) * 8;

    for (int kt = 0; kt < ntiles; kt++) {
        CP_WAIT0();
        __syncthreads();                 // tile kt visible; old buffer free
        if (kt + 1 < ntiles) {
            stage_tile(sb + SM_KV + ((kt + 1) & 1) * STAGE, bh, (kt + 1) << 6, tid);
            CP_COMMIT();
        }
        const uint32_t kb = sb + SM_KV + (kt & 1) * STAGE;  // KHI|KLO|VHI|VLO

        // ---- S = Q K^T (3-pass split) ----
        float s[8][4];
#pragma unroll
        for (int j = 0; j < 8; j++) {
#pragma unroll
            for (int e = 0; e < 4; e++) s[j][e] = 0.0f;
#pragma unroll
            for (int kk = 0; kk < 4; kk++) {
                const int rr = 8 * j + krow;
                uint32_t off = rr * 128 + (((2 * kk + ksel) ^ krow) << 4);
                uint32_t kbh[2], kbl[2];
                ldsm2(kbh[0], kbh[1], kb + off);
                ldsm2(kbl[0], kbl[1], kb + 8192 + off);
                mma_bf16(s[j], qh[kk], kbh);
                mma_bf16(s[j], qh[kk], kbl);
                mma_bf16(s[j], ql[kk], kbh);
            }
        }

        // ---- softmax: p = exp(10*tanh(s/8) - 10)  (Pade + 1 ex2 + 1 rcp) ----
#pragma unroll
        for (int j = 0; j < 8; j++) {
#pragma unroll
            for (int e = 0; e < 4; e++) {
                float p = softmax_p(s[j][e]);
                s[j][e] = p;
                if ((e & 2) == 0) lsum_lo += p; else lsum_hi += p;
            }
        }

        // ---- O += P V (3-pass split) ----
#pragma unroll
        for (int kk = 0; kk < 4; kk++) {
            const int j0 = 2 * kk;
            uint32_t pah[4], pal[4];
            split2(s[j0][0],     s[j0][1],     pah[0], pal[0]);
            split2(s[j0][2],     s[j0][3],     pah[1], pal[1]);
            split2(s[j0 + 1][0], s[j0 + 1][1], pah[2], pal[2]);
            split2(s[j0 + 1][2], s[j0 + 1][3], pah[3], pal[3]);
#pragma unroll
            for (int j = 0; j < 8; j++) {
                const int rr = 16 * kk + vrow;
                uint32_t off = rr * 128 + ((j ^ (vrow & 7)) << 4);
                uint32_t vbh[2], vbl[2];
                ldsm2t(vbh[0], vbh[1], kb + 16384 + off);
                ldsm2t(vbl[0], vbl[1], kb + 24576 + off);
                mma_bf16(o[j], pah, vbh);
                mma_bf16(o[j], pah, vbl);
                mma_bf16(o[j], pal, vbh);
            }
        }
    }

    // ---- epilogue: reduce l, remove pad bias, scale, store ----
    lsum_lo += __shfl_xor_sync(0xffffffffu, lsum_lo, 1);
    lsum_lo += __shfl_xor_sync(0xffffffffu, lsum_lo, 2);
    lsum_hi += __shfl_xor_sync(0xffffffffu, lsum_hi, 1);
    lsum_hi += __shfl_xor_sync(0xffffffffu, lsum_hi, 2);
    const float padbias = (float)(ntiles * 64 - cnt) * EXP_M10;
    const float inv_lo = 1.0f / (lsum_lo - padbias);
    const float inv_hi = 1.0f / (lsum_hi - padbias);

    const size_t row_lo = ((size_t)bh << 11) + q0 + R0 + gid;
    const size_t row_hi = row_lo + 8;
#pragma unroll
    for (int j = 0; j < 8; j++) {
        int col = 8 * j + 2 * tig;
        *(float2*)(out + row_lo * 64 + col) = make_float2(o[j][0] * inv_lo, o[j][1] * inv_lo);
        *(float2*)(out + row_hi * 64 + col) = make_float2(o[j][2] * inv_hi, o[j][3] * inv_hi);
    }
}

extern "C" void kernel_launch(void* const* d_in, const int* in_sizes, int n_in,
                              void* d_out, int out_size)
{
    const float* Q = (const float*)d_in[0];
    const float* K = (const float*)d_in[1];
    const float* V = (const float*)d_in[2];
    const unsigned char* mraw = (const unsigned char*)d_in[3];
    float* out = (float*)d_out;

    build_idx<<<8, 1024>>>(mraw);
    {
        dim3 g(128, 64);
        convert_kv<<<g, 256>>>(K, V);
    }
    cudaFuncSetAttribute(attn_mma, cudaFuncAttributeMaxDynamicSharedMemorySize, SM_TOTAL);
    dim3 grid(16, 64);                   // (q tiles of 128, B*H)
    attn_mma<<<grid, 256, SM_TOTAL>>>(Q, out);
}

// round 11
// speedup vs baseline: 1.7672x; 1.7672x over previous
#include <cuda_runtime.h>
#include <cuda_bf16.h>
#include <cstdint>

// DotProductAttention B=8,H=8,N=2048,D=64 fp32 — R8.
// Hot loop = R5 exactly (benched 293.6us: x2 ldmatrix, __expf softmax,
// cp.async double-buffer, fixed-max softmax via logits<=10).
// Pre-pass: single merged prep_kv kernel (per-(b,h) block: in-smem mask
// compaction + gather/convert K,V -> bf16 hi/lo, early-exit past padded cnt).
// Epilogue keeps exact pad-bias correction on l.

#define SM_QHI 0
#define SM_QLO 16384
#define SM_KV  32768            // 2 stages x 32KB: [KHI|KLO|VHI|VLO] 8KB each
#define STAGE  32768
#define SM_TOTAL (SM_KV + 2 * STAGE)   // 96KB

#define EXP_M10 4.5399929762e-05f      // e^-10 (pad-slot p value)

__device__ int g_cnt[8];
__device__ unsigned char KCH[1 << 24];   // 16MB each: [bh][slot][64 bf16]
__device__ unsigned char KCL[1 << 24];
__device__ unsigned char VCH[1 << 24];
__device__ unsigned char VCL[1 << 24];

// ---- helpers ----
__device__ __forceinline__ uint32_t smem_u32(const void* p) {
    uint32_t a;
    asm("{ .reg .u64 t; cvta.to.shared.u64 t, %1; cvt.u32.u64 %0, t; }" : "=r"(a) : "l"(p));
    return a;
}
__device__ __forceinline__ void split2(float a, float b, uint32_t& hi, uint32_t& lo) {
    uint32_t h;
    asm("cvt.rn.bf16x2.f32 %0, %1, %2;" : "=r"(h) : "f"(b), "f"(a));
    float ah = __uint_as_float(h << 16);
    float bh = __uint_as_float(h & 0xffff0000u);
    asm("cvt.rn.bf16x2.f32 %0, %1, %2;" : "=r"(lo) : "f"(b - bh), "f"(a - ah));
    hi = h;
}
__device__ __forceinline__ void mma_bf16(float* d, const uint32_t* a, const uint32_t* b) {
    asm volatile("mma.sync.aligned.m16n8k16.row.col.f32.bf16.bf16.f32 "
                 "{%0,%1,%2,%3}, {%4,%5,%6,%7}, {%8,%9}, {%0,%1,%2,%3};"
                 : "+f"(d[0]), "+f"(d[1]), "+f"(d[2]), "+f"(d[3])
                 : "r"(a[0]), "r"(a[1]), "r"(a[2]), "r"(a[3]), "r"(b[0]), "r"(b[1]));
}
__device__ __forceinline__ void ldsm2(uint32_t& r0, uint32_t& r1, uint32_t addr) {
    asm volatile("ldmatrix.sync.aligned.m8n8.x2.shared.b16 {%0,%1}, [%2];"
                 : "=r"(r0), "=r"(r1) : "r"(addr));
}
__device__ __forceinline__ void ldsm2t(uint32_t& r0, uint32_t& r1, uint32_t addr) {
    asm volatile("ldmatrix.sync.aligned.m8n8.x2.trans.shared.b16 {%0,%1}, [%2];"
                 : "=r"(r0), "=r"(r1) : "r"(addr));
}
__device__ __forceinline__ void ldsm4(uint32_t* r, uint32_t addr) {
    asm volatile("ldmatrix.sync.aligned.m8n8.x4.shared.b16 {%0,%1,%2,%3}, [%4];"
                 : "=r"(r[0]), "=r"(r[1]), "=r"(r[2]), "=r"(r[3]) : "r"(addr));
}

// ---- merged pre-pass: one block per (b,h) ----
// Phase A: in-smem compaction of this batch's unmasked keys (redundant per head,
//          all 64 blocks run in parallel). Phase B: gather+convert K/V rows into
//          compacted bf16 hi/lo global buffers, zero-padded to 64-slot tiles.
__global__ void __launch_bounds__(1024)
prep_kv(const float* __restrict__ K, const float* __restrict__ V,
        const unsigned char* __restrict__ mraw)
{
    __shared__ int wsum[32];
    __shared__ int s_idx[2048];
    const int bh = blockIdx.x;                 // 0..63
    const int b  = bh >> 3;
    const int t  = threadIdx.x;                // 1024 threads
    const int lane = t & 31, w = t >> 5;

    // mask dtype detection (bool-as-u8 vs bool-as-i32); first 4KB is safe either way
    int mynz = 0;
#pragma unroll
    for (int k = 0; k < 4; k++) {
        int i = t * 4 + k;
        if ((i & 3) && mraw[i]) mynz = 1;
    }
    const int is_u8 = __syncthreads_or(mynz);

    int m0, m1;
    if (is_u8) {
        m0 = mraw[b * 2048 + 2 * t];
        m1 = mraw[b * 2048 + 2 * t + 1];
    } else {
        const int* mi = (const int*)mraw;
        m0 = mi[b * 2048 + 2 * t];
        m1 = mi[b * 2048 + 2 * t + 1];
    }
    const int f0 = (m0 == 0), f1 = (m1 == 0);
    const int pair = f0 + f1;

    int sc = pair;                             // inclusive warp scan
#pragma unroll
    for (int d = 1; d < 32; d <<= 1) {
        int v = __shfl_up_sync(0xffffffffu, sc, d);
        if (lane >= d) sc += v;
    }
    if (lane == 31) wsum[w] = sc;
    __syncthreads();
    if (w == 0) {
        int s2 = wsum[lane];
#pragma unroll
        for (int d = 1; d < 32; d <<= 1) {
            int u = __shfl_up_sync(0xffffffffu, s2, d);
            if (lane >= d) s2 += u;
        }
        wsum[lane] = s2;
    }
    __syncthreads();
    int base = (w ? wsum[w - 1] : 0) + sc - pair;
    if (f0) s_idx[base++] = 2 * t;
    if (f1) s_idx[base] = 2 * t + 1;
    const int cnt = wsum[31];
    if (t == 0) g_cnt[b] = cnt;                // duplicate writes, same value
    __syncthreads();

    // Phase B: convert this bh's K/V (padded region zero-filled)
    const int padded = (cnt + 63) & ~63;
    for (int idx = t; idx < padded * 16; idx += 1024) {
        const int slot = idx >> 4;
        const int c4   = (idx & 15) << 2;
        const size_t doff = ((((size_t)bh << 11) + slot) << 7) + c4 * 2;
        uint32_t kh0 = 0, kl0 = 0, kh1 = 0, kl1 = 0;
        uint32_t vh0 = 0, vl0 = 0, vh1 = 0, vl1 = 0;
        if (slot < cnt) {
            const int row = s_idx[slot];
            const float4 kk = *(const float4*)(K + ((((size_t)bh << 11) + row) << 6) + c4);
            const float4 vv = *(const float4*)(V + ((((size_t)bh << 11) + row) << 6) + c4);
            split2(kk.x, kk.y, kh0, kl0); split2(kk.z, kk.w, kh1, kl1);
            split2(vv.x, vv.y, vh0, vl0); split2(vv.z, vv.w, vh1, vl1);
        }
        *(uint2*)(KCH + doff) = make_uint2(kh0, kh1);
        *(uint2*)(KCL + doff) = make_uint2(kl0, kl1);
        *(uint2*)(VCH + doff) = make_uint2(vh0, vh1);
        *(uint2*)(VCL + doff) = make_uint2(vl0, vl1);
    }
}

// ---- cp.async staging of one 64-key tile (K/V hi/lo) into a smem stage ----
__device__ __forceinline__ void stage_tile(uint32_t sdst, int bh, int kv0, int tid)
{
#pragma unroll
    for (int it = 0; it < 8; it++) {
        const int tensor = it >> 1;
        const int cc = ((it & 1) << 8) + tid;            // 0..511
        const int r = cc >> 3, ch = cc & 7;
        const unsigned char* g = (tensor == 0) ? KCH : (tensor == 1) ? KCL
                               : (tensor == 2) ? VCH : VCL;
        const unsigned char* src = g + ((((size_t)bh << 11) + kv0 + r) << 7) + (ch << 4);
        uint32_t dst = sdst + tensor * 8192 + r * 128 + ((ch ^ (r & 7)) << 4);
        asm volatile("cp.async.cg.shared.global [%0], [%1], 16;"
                     :: "r"(dst), "l"(src) : "memory");
    }
}
#define CP_COMMIT() asm volatile("cp.async.commit_group;" ::: "memory")
#define CP_WAIT0()  asm volatile("cp.async.wait_group 0;" ::: "memory")

// ---- main kernel: 256 threads, 8 warps, 128 q-rows per CTA ----
__global__ void __launch_bounds__(256, 2)
attn_mma(const float* __restrict__ Q, float* __restrict__ out)
{
    extern __shared__ char smem[];
    const uint32_t sb = smem_u32(smem);

    const int tid  = threadIdx.x;
    const int warp = tid >> 5;
    const int lane = tid & 31;
    const int gid  = lane >> 2;
    const int tig  = lane & 3;
    const int R0   = warp << 4;

    const int bh = blockIdx.y;
    const int b  = bh >> 3;
    const int q0 = blockIdx.x << 7;      // 128-row q tile

    const int cnt    = g_cnt[b];
    const int ntiles = (cnt + 63) >> 6;

    const float* Qg = Q + ((((size_t)bh << 11) + q0) << 6);

    // stage tile 0 first (overlaps with Q conversion below)
    stage_tile(sb + SM_KV, bh, 0, tid);
    CP_COMMIT();

    // ---- Q -> smem (hi/lo bf16, XOR swizzle) ----
#pragma unroll
    for (int it = 0; it < 8; it++) {
        int idx = it * 256 + tid;        // 2048 float4 slots: 128 rows x 16
        int r   = idx >> 4;
        int c4  = (idx & 15) << 2;
        float4 v = *(const float4*)(Qg + (r << 6) + c4);
        uint32_t h0, l0, h1, l1;
        split2(v.x, v.y, h0, l0);
        split2(v.z, v.w, h1, l1);
        uint32_t off = r * 128 + ((c4 * 2) ^ ((r & 7) << 4));
        *(uint2*)(smem + SM_QHI + off) = make_uint2(h0, h1);
        *(uint2*)(smem + SM_QLO + off) = make_uint2(l0, l1);
    }
    __syncthreads();

    // ---- Q A-fragments in registers for the whole kernel ----
    uint32_t qh[4][4], ql[4][4];
    {
        const int arow = R0 + (lane & 7) + ((lane >> 3) & 1) * 8;
        const int asw  = lane & 7;
#pragma unroll
        for (int kk = 0; kk < 4; kk++) {
            uint32_t off = arow * 128 + ((((2 * kk + (lane >> 4)) ^ asw)) << 4);
            ldsm4(qh[kk], sb + SM_QHI + off);
            ldsm4(ql[kk], sb + SM_QLO + off);
        }
    }

    float o[8][4];
#pragma unroll
    for (int j = 0; j < 8; j++)
#pragma unroll
        for (int e = 0; e < 4; e++) o[j][e] = 0.0f;
    float lsum_lo = 0.0f, lsum_hi = 0.0f;

    const int krow = lane & 7;
    const int ksel = (lane >> 3) & 1;
    const int vrow = (lane & 7) + ((lane >> 3) & 1) * 8;

    for (int kt = 0; kt < ntiles; kt++) {
        CP_WAIT0();
        __syncthreads();                 // tile kt visible; old buffer free
        if (kt + 1 < ntiles) {
            stage_tile(sb + SM_KV + ((kt + 1) & 1) * STAGE, bh, (kt + 1) << 6, tid);
            CP_COMMIT();
        }
        const uint32_t kb = sb + SM_KV + (kt & 1) * STAGE;  // KHI|KLO|VHI|VLO

        // ---- S = Q K^T (3-pass split) ----
        float s[8][4];
#pragma unroll
        for (int j = 0; j < 8; j++) {
#pragma unroll
            for (int e = 0; e < 4; e++) s[j][e] = 0.0f;
#pragma unroll
            for (int kk = 0; kk < 4; kk++) {
                const int rr = 8 * j + krow;
                uint32_t off = rr * 128 + (((2 * kk + ksel) ^ krow) << 4);
                uint32_t kbh[2], kbl[2];
                ldsm2(kbh[0], kbh[1], kb + off);
                ldsm2(kbl[0], kbl[1], kb + 8192 + off);
                mma_bf16(s[j], qh[kk], kbh);
                mma_bf16(s[j], qh[kk], kbl);
                mma_bf16(s[j], ql[kk], kbh);
            }
        }

        // ---- softmax: p = exp(10*tanh(s/8) - 10); pad slots give e^-10 ----
#pragma unroll
        for (int j = 0; j < 8; j++) {
#pragma unroll
            for (int e = 0; e < 4; e++) {
                float eu = __expf(0.25f * s[j][e]);
                float p  = __expf(-__fdividef(20.0f, eu + 1.0f));
                s[j][e] = p;
                if ((e & 2) == 0) lsum_lo += p; else lsum_hi += p;
            }
        }

        // ---- O += P V (3-pass split) ----
#pragma unroll
        for (int kk = 0; kk < 4; kk++) {
            const int j0 = 2 * kk;
            uint32_t pah[4], pal[4];
            split2(s[j0][0],     s[j0][1],     pah[0], pal[0]);
            split2(s[j0][2],     s[j0][3],     pah[1], pal[1]);
            split2(s[j0 + 1][0], s[j0 + 1][1], pah[2], pal[2]);
            split2(s[j0 + 1][2], s[j0 + 1][3], pah[3], pal[3]);
#pragma unroll
            for (int j = 0; j < 8; j++) {
                const int rr = 16 * kk + vrow;
                uint32_t off = rr * 128 + ((j ^ (vrow & 7)) << 4);
                uint32_t vbh[2], vbl[2];
                ldsm2t(vbh[0], vbh[1], kb + 16384 + off);
                ldsm2t(vbl[0], vbl[1], kb + 24576 + off);
                mma_bf16(o[j], pah, vbh);
                mma_bf16(o[j], pah, vbl);
                mma_bf16(o[j], pal, vbh);
            }
        }
    }

    // ---- epilogue: reduce l, remove pad bias, scale, store ----
    lsum_lo += __shfl_xor_sync(0xffffffffu, lsum_lo, 1);
    lsum_lo += __shfl_xor_sync(0xffffffffu, lsum_lo, 2);
    lsum_hi += __shfl_xor_sync(0xffffffffu, lsum_hi, 1);
    lsum_hi += __shfl_xor_sync(0xffffffffu, lsum_hi, 2);
    const float padbias = (float)(ntiles * 64 - cnt) * EXP_M10;
    const float inv_lo = 1.0f / (lsum_lo - padbias);
    const float inv_hi = 1.0f / (lsum_hi - padbias);

    const size_t row_lo = ((size_t)bh << 11) + q0 + R0 + gid;
    const size_t row_hi = row_lo + 8;
#pragma unroll
    for (int j = 0; j < 8; j++) {
        int col = 8 * j + 2 * tig;
        *(float2*)(out + row_lo * 64 + col) = make_float2(o[j][0] * inv_lo, o[j][1] * inv_lo);
        *(float2*)(out + row_hi * 64 + col) = make_float2(o[j][2] * inv_hi, o[j][3] * inv_hi);
    }
}

extern "C" void kernel_launch(void* const* d_in, const int* in_sizes, int n_in,
                              void* d_out, int out_size)
{
    const float* Q = (const float*)d_in[0];
    const float* K = (const float*)d_in[1];
    const float* V = (const float*)d_in[2];
    const unsigned char* mraw = (const unsigned char*)d_in[3];
    float* out = (float*)d_out;

    prep_kv<<<64, 1024>>>(K, V, mraw);

    cudaFuncSetAttribute(attn_mma, cudaFuncAttributeMaxDynamicSharedMemorySize, SM_TOTAL);
    dim3 grid(16, 64);                   // (q tiles of 128, B*H)
    attn_mma<<<grid, 256, SM_TOTAL>>>(Q, out);
}